// round 1
// baseline (speedup 1.0000x reference)
#include <cuda_runtime.h>
#include <cuda_bf16.h>
#include <math.h>

// Problem constants
#define BB 2
#define SS 2048
#define DD 1024
#define NH 16
#define DKH 64
#define MROWS (BB * SS)   // 4096

// ---------------- scratch (device globals; no allocation allowed) ----------------
__device__ float g_Q[MROWS * DD];
__device__ float g_K[MROWS * DD];
__device__ float g_V[MROWS * DD];
__device__ float g_X[MROWS * DD];

// ---------------- SGEMM: C[M,N] = A[M,K] @ W[N,K]^T + bias[N] ----------------
// BM=128, BN=128, BK=16, 256 threads, each computes 8x8.
__global__ __launch_bounds__(256) void sgemm_bias_kernel(
    const float* __restrict__ A, const float* __restrict__ W,
    const float* __restrict__ bias, float* __restrict__ C,
    int M, int N, int K)
{
    __shared__ float As[16][128];
    __shared__ float Bs[16][128];

    const int tid = threadIdx.x;
    const int m0 = blockIdx.y * 128;
    const int n0 = blockIdx.x * 128;
    const int tx = tid & 15;       // 0..15 (col group)
    const int ty = tid >> 4;       // 0..15 (row group)

    float acc[8][8];
    #pragma unroll
    for (int i = 0; i < 8; i++)
        #pragma unroll
        for (int j = 0; j < 8; j++) acc[i][j] = 0.f;

    for (int k0 = 0; k0 < K; k0 += 16) {
        // cooperative load: 128 rows x 16 cols for A-tile and W-tile
        #pragma unroll
        for (int u = 0; u < 2; u++) {
            int idx = tid + u * 256;      // 0..511
            int row = idx >> 2;           // 0..127
            int c   = idx & 3;            // 0..3 (float4 group along K)
            float4 a4 = *(const float4*)&A[(size_t)(m0 + row) * K + k0 + c * 4];
            As[c*4+0][row] = a4.x; As[c*4+1][row] = a4.y;
            As[c*4+2][row] = a4.z; As[c*4+3][row] = a4.w;
            float4 w4 = *(const float4*)&W[(size_t)(n0 + row) * K + k0 + c * 4];
            Bs[c*4+0][row] = w4.x; Bs[c*4+1][row] = w4.y;
            Bs[c*4+2][row] = w4.z; Bs[c*4+3][row] = w4.w;
        }
        __syncthreads();

        #pragma unroll
        for (int kk = 0; kk < 16; kk++) {
            float ra[8], rb[8];
            #pragma unroll
            for (int i = 0; i < 8; i += 4) {
                float4 t = *(const float4*)&As[kk][ty * 8 + i];
                ra[i] = t.x; ra[i+1] = t.y; ra[i+2] = t.z; ra[i+3] = t.w;
            }
            #pragma unroll
            for (int j = 0; j < 8; j += 4) {
                float4 t = *(const float4*)&Bs[kk][tx * 8 + j];
                rb[j] = t.x; rb[j+1] = t.y; rb[j+2] = t.z; rb[j+3] = t.w;
            }
            #pragma unroll
            for (int i = 0; i < 8; i++)
                #pragma unroll
                for (int j = 0; j < 8; j++)
                    acc[i][j] += ra[i] * rb[j];
        }
        __syncthreads();
    }

    // epilogue: add bias, store
    float bb[8];
    #pragma unroll
    for (int j = 0; j < 8; j++) bb[j] = bias[n0 + tx * 8 + j];

    #pragma unroll
    for (int i = 0; i < 8; i++) {
        size_t rowoff = (size_t)(m0 + ty * 8 + i) * N + n0 + tx * 8;
        #pragma unroll
        for (int jc = 0; jc < 2; jc++) {
            float4 o;
            o.x = acc[i][jc*4+0] + bb[jc*4+0];
            o.y = acc[i][jc*4+1] + bb[jc*4+1];
            o.z = acc[i][jc*4+2] + bb[jc*4+2];
            o.w = acc[i][jc*4+3] + bb[jc*4+3];
            *(float4*)&C[rowoff + jc * 4] = o;
        }
    }
}

// ---------------- Flash attention (causal), fp32 ----------------
// grid: (S/128, H, B); 128 threads; each thread owns 1 query row.
// K/V tiles of 64 rows in SMEM (broadcast reads), scores staged in padded SMEM.
#define QT 128
#define KT 64
#define FLASH_SMEM ((KT*DKH*2 + QT*(KT+1)) * 4)   // 66048 bytes

__global__ __launch_bounds__(128) void flash_kernel(
    const float* __restrict__ Q, const float* __restrict__ K,
    const float* __restrict__ V, float* __restrict__ O)
{
    extern __shared__ float smem[];
    float* Ks = smem;                    // [KT][DKH]
    float* Vs = smem + KT * DKH;         // [KT][DKH]
    float* Ss = smem + 2 * KT * DKH;     // [QT][KT+1]

    const int tid = threadIdx.x;
    const int qt = blockIdx.x;
    const int h  = blockIdx.y;
    const int b  = blockIdx.z;
    const int r  = qt * QT + tid;        // global query row this thread owns
    const float scale = 0.125f;          // 1/sqrt(64)

    const size_t qoff = ((size_t)(b * SS + r)) * DD + h * DKH;

    float qreg[DKH];
    #pragma unroll
    for (int i = 0; i < DKH / 4; i++) {
        float4 t = *(const float4*)(Q + qoff + i * 4);
        qreg[i*4+0] = t.x * scale; qreg[i*4+1] = t.y * scale;
        qreg[i*4+2] = t.z * scale; qreg[i*4+3] = t.w * scale;
    }

    float m = -1e30f, l = 0.f;
    float acc[DKH];
    #pragma unroll
    for (int d = 0; d < DKH; d++) acc[d] = 0.f;

    float* myS = &Ss[tid * (KT + 1)];
    const int ntiles = 2 * qt + 2;       // causal: cover up to row qt*128+127

    for (int t = 0; t < ntiles; t++) {
        const int j0 = t * KT;
        __syncthreads();   // protect prior iteration's SMEM reads
        // cooperative load of K and V tiles (64 rows x 64 floats each)
        const size_t base = ((size_t)(b * SS + j0)) * DD + h * DKH;
        #pragma unroll
        for (int u = 0; u < 8; u++) {
            int idx = tid + u * 128;     // 0..1023
            int row = idx >> 4;          // 0..63
            int c   = idx & 15;          // float4 group
            *(float4*)&Ks[row * DKH + c * 4] =
                *(const float4*)(K + base + (size_t)row * DD + c * 4);
            *(float4*)&Vs[row * DKH + c * 4] =
                *(const float4*)(V + base + (size_t)row * DD + c * 4);
        }
        __syncthreads();

        // pass 1: scores + tile max
        float tmax = -1e30f;
        #pragma unroll 4
        for (int j = 0; j < KT; j++) {
            const float* kr = &Ks[j * DKH];
            float s = 0.f;
            #pragma unroll
            for (int d4 = 0; d4 < DKH / 4; d4++) {
                float4 k4 = *(const float4*)(kr + d4 * 4);
                s += qreg[d4*4+0] * k4.x + qreg[d4*4+1] * k4.y
                   + qreg[d4*4+2] * k4.z + qreg[d4*4+3] * k4.w;
            }
            if (j0 + j > r) s = -1e30f;  // causal mask
            myS[j] = s;
            tmax = fmaxf(tmax, s);
        }

        const float mnew = fmaxf(m, tmax);
        const float corr = __expf(m - mnew);
        l *= corr;
        #pragma unroll
        for (int d = 0; d < DKH; d++) acc[d] *= corr;
        m = mnew;

        // pass 2: P@V
        #pragma unroll 2
        for (int j = 0; j < KT; j++) {
            float p = __expf(myS[j] - mnew);
            l += p;
            const float* vr = &Vs[j * DKH];
            #pragma unroll
            for (int d4 = 0; d4 < DKH / 4; d4++) {
                float4 v4 = *(const float4*)(vr + d4 * 4);
                acc[d4*4+0] += p * v4.x; acc[d4*4+1] += p * v4.y;
                acc[d4*4+2] += p * v4.z; acc[d4*4+3] += p * v4.w;
            }
        }
    }

    const float inv = 1.0f / l;
    #pragma unroll
    for (int d4 = 0; d4 < DKH / 4; d4++) {
        float4 o;
        o.x = acc[d4*4+0] * inv; o.y = acc[d4*4+1] * inv;
        o.z = acc[d4*4+2] * inv; o.w = acc[d4*4+3] * inv;
        *(float4*)(O + qoff + d4 * 4) = o;
    }
}

// ---------------- launch ----------------
extern "C" void kernel_launch(void* const* d_in, const int* in_sizes, int n_in,
                              void* d_out, int out_size)
{
    const float* q  = (const float*)d_in[0];
    const float* k  = (const float*)d_in[1];
    const float* v  = (const float*)d_in[2];
    // d_in[3] = mask (causal, known at compile time — unused)
    const float* wq = (const float*)d_in[4];
    const float* bq = (const float*)d_in[5];
    const float* wk = (const float*)d_in[6];
    const float* bk = (const float*)d_in[7];
    const float* wv = (const float*)d_in[8];
    const float* bv = (const float*)d_in[9];
    const float* wo = (const float*)d_in[10];
    const float* bo = (const float*)d_in[11];
    float* out = (float*)d_out;

    void *pQ, *pK, *pV, *pX;
    cudaGetSymbolAddress(&pQ, g_Q);
    cudaGetSymbolAddress(&pK, g_K);
    cudaGetSymbolAddress(&pV, g_V);
    cudaGetSymbolAddress(&pX, g_X);
    float* gQ = (float*)pQ;
    float* gK = (float*)pK;
    float* gV = (float*)pV;
    float* gX = (float*)pX;

    cudaFuncSetAttribute(flash_kernel,
                         cudaFuncAttributeMaxDynamicSharedMemorySize, FLASH_SMEM);

    dim3 ggrid(DD / 128, MROWS / 128);   // (8, 32)
    sgemm_bias_kernel<<<ggrid, 256>>>(q, wq, bq, gQ, MROWS, DD, DD);
    sgemm_bias_kernel<<<ggrid, 256>>>(k, wk, bk, gK, MROWS, DD, DD);
    sgemm_bias_kernel<<<ggrid, 256>>>(v, wv, bv, gV, MROWS, DD, DD);

    dim3 fgrid(SS / QT, NH, BB);         // (16, 16, 2)
    flash_kernel<<<fgrid, 128, FLASH_SMEM>>>(gQ, gK, gV, gX);

    sgemm_bias_kernel<<<ggrid, 256>>>(gX, wo, bo, out, MROWS, DD, DD);
}

// round 3
// speedup vs baseline: 1.1802x; 1.1802x over previous
#include <cuda_runtime.h>
#include <cuda_bf16.h>
#include <math.h>
#include <stdint.h>

// Problem constants
#define BB 2
#define SS 2048
#define DD 1024
#define NH 16
#define DKH 64
#define MROWS (BB * SS)   // 4096

// ---------------- scratch (device globals; no allocation allowed) ----------------
__device__ float g_Q[MROWS * DD];
__device__ float g_K[MROWS * DD];
__device__ float g_V[MROWS * DD];
__device__ float g_X[MROWS * DD];

__device__ __forceinline__ uint32_t f2tf32(float x) {
    uint32_t r;
    asm("cvt.rna.tf32.f32 %0, %1;" : "=r"(r) : "f"(x));
    return r;
}

// ---------------- TF32 tensor-core GEMM: C[M,N] = A[M,K] @ W[N,K]^T + bias ----------------
// BM=128, BN=128, BK=32. 256 threads = 8 warps in 2(m) x 4(n) grid; warp tile 64x32.
// Each warp: 4x4 grid of mma.m16n8k8.tf32. SMEM stride 129 -> conflict-free frag loads.
#define GBM 128
#define GBN 128
#define GBK 32
#define GSTR 129

__global__ __launch_bounds__(256) void gemm_tf32_kernel(
    const float* __restrict__ A, const float* __restrict__ W,
    const float* __restrict__ bias, float* __restrict__ C,
    int M, int N, int K)
{
    __shared__ uint32_t As[GBK * GSTR];
    __shared__ uint32_t Bs[GBK * GSTR];

    const int tid  = threadIdx.x;
    const int lane = tid & 31;
    const int warp = tid >> 5;
    const int wm = (warp & 1) * 64;   // warp row offset in block tile
    const int wn = (warp >> 1) * 32;  // warp col offset
    const int m0 = blockIdx.y * GBM;
    const int n0 = blockIdx.x * GBN;
    const int lr = lane >> 2;         // 0..7
    const int lc = lane & 3;          // 0..3

    float acc[4][4][4];
    #pragma unroll
    for (int i = 0; i < 4; i++)
        #pragma unroll
        for (int j = 0; j < 4; j++)
            #pragma unroll
            for (int t = 0; t < 4; t++) acc[i][j][t] = 0.f;

    for (int k0 = 0; k0 < K; k0 += GBK) {
        // cooperative load: 128 rows x 32 cols each, stored transposed [k][row]
        #pragma unroll
        for (int u = 0; u < 4; u++) {
            int idx = tid + u * 256;      // 0..1023
            int row = idx >> 3;           // 0..127
            int c   = idx & 7;            // float4 group along K
            float4 a4 = *(const float4*)&A[(size_t)(m0 + row) * K + k0 + c * 4];
            As[(c*4+0)*GSTR + row] = f2tf32(a4.x);
            As[(c*4+1)*GSTR + row] = f2tf32(a4.y);
            As[(c*4+2)*GSTR + row] = f2tf32(a4.z);
            As[(c*4+3)*GSTR + row] = f2tf32(a4.w);
            float4 b4 = *(const float4*)&W[(size_t)(n0 + row) * K + k0 + c * 4];
            Bs[(c*4+0)*GSTR + row] = f2tf32(b4.x);
            Bs[(c*4+1)*GSTR + row] = f2tf32(b4.y);
            Bs[(c*4+2)*GSTR + row] = f2tf32(b4.z);
            Bs[(c*4+3)*GSTR + row] = f2tf32(b4.w);
        }
        __syncthreads();

        #pragma unroll
        for (int ks = 0; ks < GBK / 8; ks++) {
            const int kb = ks * 8;
            uint32_t a[4][4], b[4][2];
            #pragma unroll
            for (int mt = 0; mt < 4; mt++) {
                int r = wm + mt * 16 + lr;
                a[mt][0] = As[(kb + lc) * GSTR + r];
                a[mt][1] = As[(kb + lc) * GSTR + r + 8];
                a[mt][2] = As[(kb + 4 + lc) * GSTR + r];
                a[mt][3] = As[(kb + 4 + lc) * GSTR + r + 8];
            }
            #pragma unroll
            for (int nt = 0; nt < 4; nt++) {
                int cn = wn + nt * 8 + lr;
                b[nt][0] = Bs[(kb + lc) * GSTR + cn];
                b[nt][1] = Bs[(kb + 4 + lc) * GSTR + cn];
            }
            #pragma unroll
            for (int mt = 0; mt < 4; mt++)
                #pragma unroll
                for (int nt = 0; nt < 4; nt++)
                    asm volatile(
                        "mma.sync.aligned.m16n8k8.row.col.f32.tf32.tf32.f32 "
                        "{%0,%1,%2,%3}, {%4,%5,%6,%7}, {%8,%9}, {%0,%1,%2,%3};"
                        : "+f"(acc[mt][nt][0]), "+f"(acc[mt][nt][1]),
                          "+f"(acc[mt][nt][2]), "+f"(acc[mt][nt][3])
                        : "r"(a[mt][0]), "r"(a[mt][1]), "r"(a[mt][2]), "r"(a[mt][3]),
                          "r"(b[nt][0]), "r"(b[nt][1]));
        }
        __syncthreads();
    }

    // epilogue: D fragment -> row = lr (+8), col = lc*2 (+1)
    #pragma unroll
    for (int nt = 0; nt < 4; nt++) {
        int col = n0 + wn + nt * 8 + lc * 2;
        float b0 = bias[col], b1 = bias[col + 1];
        #pragma unroll
        for (int mt = 0; mt < 4; mt++) {
            int r0 = m0 + wm + mt * 16 + lr;
            float2 o0 = make_float2(acc[mt][nt][0] + b0, acc[mt][nt][1] + b1);
            *(float2*)&C[(size_t)r0 * N + col] = o0;
            float2 o1 = make_float2(acc[mt][nt][2] + b0, acc[mt][nt][3] + b1);
            *(float2*)&C[(size_t)(r0 + 8) * N + col] = o1;
        }
    }
}

// ---------------- Flash attention (causal), fp32 ----------------
#define QT 128
#define KT 64
#define FLASH_SMEM ((KT*DKH*2 + QT*(KT+1)) * 4)   // 66048 bytes

__global__ __launch_bounds__(128) void flash_kernel(
    const float* __restrict__ Q, const float* __restrict__ K,
    const float* __restrict__ V, float* __restrict__ O)
{
    extern __shared__ float smem[];
    float* Ks = smem;                    // [KT][DKH]
    float* Vs = smem + KT * DKH;         // [KT][DKH]
    float* Ss = smem + 2 * KT * DKH;     // [QT][KT+1]

    const int tid = threadIdx.x;
    const int qt = blockIdx.x;
    const int h  = blockIdx.y;
    const int b  = blockIdx.z;
    const int r  = qt * QT + tid;        // global query row this thread owns
    const float scale = 0.125f;          // 1/sqrt(64)

    const size_t qoff = ((size_t)(b * SS + r)) * DD + h * DKH;

    float qreg[DKH];
    #pragma unroll
    for (int i = 0; i < DKH / 4; i++) {
        float4 t = *(const float4*)(Q + qoff + i * 4);
        qreg[i*4+0] = t.x * scale; qreg[i*4+1] = t.y * scale;
        qreg[i*4+2] = t.z * scale; qreg[i*4+3] = t.w * scale;
    }

    float m = -1e30f, l = 0.f;
    float acc[DKH];
    #pragma unroll
    for (int d = 0; d < DKH; d++) acc[d] = 0.f;

    float* myS = &Ss[tid * (KT + 1)];
    const int ntiles = 2 * qt + 2;       // causal

    for (int t = 0; t < ntiles; t++) {
        const int j0 = t * KT;
        __syncthreads();
        const size_t base = ((size_t)(b * SS + j0)) * DD + h * DKH;
        #pragma unroll
        for (int u = 0; u < 8; u++) {
            int idx = tid + u * 128;
            int row = idx >> 4;
            int c   = idx & 15;
            *(float4*)&Ks[row * DKH + c * 4] =
                *(const float4*)(K + base + (size_t)row * DD + c * 4);
            *(float4*)&Vs[row * DKH + c * 4] =
                *(const float4*)(V + base + (size_t)row * DD + c * 4);
        }
        __syncthreads();

        float tmax = -1e30f;
        #pragma unroll 4
        for (int j = 0; j < KT; j++) {
            const float* kr = &Ks[j * DKH];
            float s = 0.f;
            #pragma unroll
            for (int d4 = 0; d4 < DKH / 4; d4++) {
                float4 k4 = *(const float4*)(kr + d4 * 4);
                s += qreg[d4*4+0] * k4.x + qreg[d4*4+1] * k4.y
                   + qreg[d4*4+2] * k4.z + qreg[d4*4+3] * k4.w;
            }
            if (j0 + j > r) s = -1e30f;
            myS[j] = s;
            tmax = fmaxf(tmax, s);
        }

        const float mnew = fmaxf(m, tmax);
        const float corr = __expf(m - mnew);
        l *= corr;
        #pragma unroll
        for (int d = 0; d < DKH; d++) acc[d] *= corr;
        m = mnew;

        #pragma unroll 2
        for (int j = 0; j < KT; j++) {
            float p = __expf(myS[j] - mnew);
            l += p;
            const float* vr = &Vs[j * DKH];
            #pragma unroll
            for (int d4 = 0; d4 < DKH / 4; d4++) {
                float4 v4 = *(const float4*)(vr + d4 * 4);
                acc[d4*4+0] += p * v4.x; acc[d4*4+1] += p * v4.y;
                acc[d4*4+2] += p * v4.z; acc[d4*4+3] += p * v4.w;
            }
        }
    }

    const float inv = 1.0f / l;
    #pragma unroll
    for (int d4 = 0; d4 < DKH / 4; d4++) {
        float4 o;
        o.x = acc[d4*4+0] * inv; o.y = acc[d4*4+1] * inv;
        o.z = acc[d4*4+2] * inv; o.w = acc[d4*4+3] * inv;
        *(float4*)(O + qoff + d4 * 4) = o;
    }
}

// ---------------- launch ----------------
extern "C" void kernel_launch(void* const* d_in, const int* in_sizes, int n_in,
                              void* d_out, int out_size)
{
    const float* q  = (const float*)d_in[0];
    const float* k  = (const float*)d_in[1];
    const float* v  = (const float*)d_in[2];
    // d_in[3] = mask (compile-time causal — unused)
    const float* wq = (const float*)d_in[4];
    const float* bq = (const float*)d_in[5];
    const float* wk = (const float*)d_in[6];
    const float* bk = (const float*)d_in[7];
    const float* wv = (const float*)d_in[8];
    const float* bv = (const float*)d_in[9];
    const float* wo = (const float*)d_in[10];
    const float* bo = (const float*)d_in[11];
    float* out = (float*)d_out;

    void *pQ, *pK, *pV, *pX;
    cudaGetSymbolAddress(&pQ, g_Q);
    cudaGetSymbolAddress(&pK, g_K);
    cudaGetSymbolAddress(&pV, g_V);
    cudaGetSymbolAddress(&pX, g_X);
    float* gQ = (float*)pQ;
    float* gK = (float*)pK;
    float* gV = (float*)pV;
    float* gX = (float*)pX;

    cudaFuncSetAttribute(flash_kernel,
                         cudaFuncAttributeMaxDynamicSharedMemorySize, FLASH_SMEM);

    dim3 ggrid(DD / GBN, MROWS / GBM);   // (8, 32)
    gemm_tf32_kernel<<<ggrid, 256>>>(q, wq, bq, gQ, MROWS, DD, DD);
    gemm_tf32_kernel<<<ggrid, 256>>>(k, wk, bk, gK, MROWS, DD, DD);
    gemm_tf32_kernel<<<ggrid, 256>>>(v, wv, bv, gV, MROWS, DD, DD);

    dim3 fgrid(SS / QT, NH, BB);         // (16, 16, 2)
    flash_kernel<<<fgrid, 128, FLASH_SMEM>>>(gQ, gK, gV, gX);

    gemm_tf32_kernel<<<ggrid, 256>>>(gX, wo, bo, out, MROWS, DD, DD);
}

// round 4
// speedup vs baseline: 2.4705x; 2.0933x over previous
#include <cuda_runtime.h>
#include <cuda_bf16.h>
#include <math.h>
#include <stdint.h>

// Problem constants
#define BB 2
#define SS 2048
#define DD 1024
#define NH 16
#define DKH 64
#define MROWS (BB * SS)   // 4096

// ---------------- scratch (device globals; no allocation allowed) ----------------
__device__ float g_Q[MROWS * DD];
__device__ float g_K[MROWS * DD];
__device__ float g_V[MROWS * DD];
__device__ float g_X[MROWS * DD];

__device__ __forceinline__ uint32_t f2tf32(float x) {
    uint32_t r;
    asm("cvt.rna.tf32.f32 %0, %1;" : "=r"(r) : "f"(x));
    return r;
}
__device__ __forceinline__ float f2tf32f(float x) {
    return __uint_as_float(f2tf32(x));
}

// ---------------- TF32 tensor-core GEMM: C[M,N] = A[M,K] @ W[N,K]^T + bias ----------------
#define GBM 128
#define GBN 128
#define GBK 32
#define GSTR 129

__global__ __launch_bounds__(256) void gemm_tf32_kernel(
    const float* __restrict__ A, const float* __restrict__ W,
    const float* __restrict__ bias, float* __restrict__ C,
    int M, int N, int K)
{
    __shared__ uint32_t As[GBK * GSTR];
    __shared__ uint32_t Bs[GBK * GSTR];

    const int tid  = threadIdx.x;
    const int lane = tid & 31;
    const int warp = tid >> 5;
    const int wm = (warp & 1) * 64;
    const int wn = (warp >> 1) * 32;
    const int m0 = blockIdx.y * GBM;
    const int n0 = blockIdx.x * GBN;
    const int lr = lane >> 2;
    const int lc = lane & 3;

    float acc[4][4][4];
    #pragma unroll
    for (int i = 0; i < 4; i++)
        #pragma unroll
        for (int j = 0; j < 4; j++)
            #pragma unroll
            for (int t = 0; t < 4; t++) acc[i][j][t] = 0.f;

    for (int k0 = 0; k0 < K; k0 += GBK) {
        #pragma unroll
        for (int u = 0; u < 4; u++) {
            int idx = tid + u * 256;
            int row = idx >> 3;
            int c   = idx & 7;
            float4 a4 = *(const float4*)&A[(size_t)(m0 + row) * K + k0 + c * 4];
            As[(c*4+0)*GSTR + row] = f2tf32(a4.x);
            As[(c*4+1)*GSTR + row] = f2tf32(a4.y);
            As[(c*4+2)*GSTR + row] = f2tf32(a4.z);
            As[(c*4+3)*GSTR + row] = f2tf32(a4.w);
            float4 b4 = *(const float4*)&W[(size_t)(n0 + row) * K + k0 + c * 4];
            Bs[(c*4+0)*GSTR + row] = f2tf32(b4.x);
            Bs[(c*4+1)*GSTR + row] = f2tf32(b4.y);
            Bs[(c*4+2)*GSTR + row] = f2tf32(b4.z);
            Bs[(c*4+3)*GSTR + row] = f2tf32(b4.w);
        }
        __syncthreads();

        #pragma unroll
        for (int ks = 0; ks < GBK / 8; ks++) {
            const int kb = ks * 8;
            uint32_t a[4][4], b[4][2];
            #pragma unroll
            for (int mt = 0; mt < 4; mt++) {
                int r = wm + mt * 16 + lr;
                a[mt][0] = As[(kb + lc) * GSTR + r];
                a[mt][1] = As[(kb + lc) * GSTR + r + 8];
                a[mt][2] = As[(kb + 4 + lc) * GSTR + r];
                a[mt][3] = As[(kb + 4 + lc) * GSTR + r + 8];
            }
            #pragma unroll
            for (int nt = 0; nt < 4; nt++) {
                int cn = wn + nt * 8 + lr;
                b[nt][0] = Bs[(kb + lc) * GSTR + cn];
                b[nt][1] = Bs[(kb + 4 + lc) * GSTR + cn];
            }
            #pragma unroll
            for (int mt = 0; mt < 4; mt++)
                #pragma unroll
                for (int nt = 0; nt < 4; nt++)
                    asm volatile(
                        "mma.sync.aligned.m16n8k8.row.col.f32.tf32.tf32.f32 "
                        "{%0,%1,%2,%3}, {%4,%5,%6,%7}, {%8,%9}, {%0,%1,%2,%3};"
                        : "+f"(acc[mt][nt][0]), "+f"(acc[mt][nt][1]),
                          "+f"(acc[mt][nt][2]), "+f"(acc[mt][nt][3])
                        : "r"(a[mt][0]), "r"(a[mt][1]), "r"(a[mt][2]), "r"(a[mt][3]),
                          "r"(b[nt][0]), "r"(b[nt][1]));
        }
        __syncthreads();
    }

    #pragma unroll
    for (int nt = 0; nt < 4; nt++) {
        int col = n0 + wn + nt * 8 + lc * 2;
        float b0 = bias[col], b1 = bias[col + 1];
        #pragma unroll
        for (int mt = 0; mt < 4; mt++) {
            int r0 = m0 + wm + mt * 16 + lr;
            float2 o0 = make_float2(acc[mt][nt][0] + b0, acc[mt][nt][1] + b1);
            *(float2*)&C[(size_t)r0 * N + col] = o0;
            float2 o1 = make_float2(acc[mt][nt][2] + b0, acc[mt][nt][3] + b1);
            *(float2*)&C[(size_t)(r0 + 8) * N + col] = o1;
        }
    }
}

// ---------------- Flash attention (causal) with TF32 mma ----------------
// CTA: 128 threads (4 warps), Q-tile 64 rows; each warp owns 16 q-rows.
// K/V tiles: 64 x 64 in SMEM, row stride 68 floats (conflict-free frags).
#define FQT 64
#define FKT 64
#define FSTR 68
#define FLASH_SMEM (4 * FQT * FSTR * 4)   // Qs,Ks,Vs,Ps = 69632 bytes

__global__ __launch_bounds__(128) void flash_mma_kernel(
    const float* __restrict__ Q, const float* __restrict__ K,
    const float* __restrict__ V, float* __restrict__ O)
{
    extern __shared__ float smem[];
    float* Qs = smem;                      // [64][FSTR] tf32 (pre-scaled)
    float* Ks = smem + FQT * FSTR;         // [64][FSTR] tf32
    float* Vs = smem + 2 * FQT * FSTR;     // [64][FSTR] tf32 (row=seq, col=dk)
    float* Ps = smem + 3 * FQT * FSTR;     // [64][FSTR] tf32 (per-warp rows)

    const int tid  = threadIdx.x;
    const int lane = tid & 31;
    const int warp = tid >> 5;
    const int lr = lane >> 2;      // 0..7
    const int lc = lane & 3;       // 0..3
    const int qt = blockIdx.x;
    const int h  = blockIdx.y;
    const int b  = blockIdx.z;
    const int q0 = qt * FQT;
    const int lw = warp * 16 + lr; // local q-row (this thread's row 0; +8 for row 1)
    const float scale = 0.125f;

    // ---- load Q tile (scaled + tf32) ----
    {
        const size_t base = ((size_t)(b * SS + q0)) * DD + h * DKH;
        #pragma unroll
        for (int u = 0; u < 8; u++) {
            int idx = tid + u * 128;
            int row = idx >> 4;
            int c   = idx & 15;
            float4 t = *(const float4*)(Q + base + (size_t)row * DD + c * 4);
            float4 o;
            o.x = f2tf32f(t.x * scale); o.y = f2tf32f(t.y * scale);
            o.z = f2tf32f(t.z * scale); o.w = f2tf32f(t.w * scale);
            *(float4*)&Qs[row * FSTR + c * 4] = o;
        }
    }

    float m0v = -1e30f, m1v = -1e30f, l0 = 0.f, l1 = 0.f;
    float o_acc[8][4];
    #pragma unroll
    for (int nt = 0; nt < 8; nt++)
        #pragma unroll
        for (int t = 0; t < 4; t++) o_acc[nt][t] = 0.f;

    const int ntiles = qt + 1;   // causal

    for (int t = 0; t < ntiles; t++) {
        __syncthreads();
        // ---- load K,V tiles ----
        const size_t base = ((size_t)(b * SS + t * FKT)) * DD + h * DKH;
        #pragma unroll
        for (int u = 0; u < 4; u++) {
            int idx = tid + u * 128;
            int row = idx >> 3;          // 0..63
            int c   = idx & 7;           // 0..7 float4 group
            float4 kt = *(const float4*)(K + base + (size_t)row * DD + c * 8);
            float4 kt2 = *(const float4*)(K + base + (size_t)row * DD + c * 8 + 4);
            float4 ko, ko2;
            ko.x = f2tf32f(kt.x); ko.y = f2tf32f(kt.y); ko.z = f2tf32f(kt.z); ko.w = f2tf32f(kt.w);
            ko2.x = f2tf32f(kt2.x); ko2.y = f2tf32f(kt2.y); ko2.z = f2tf32f(kt2.z); ko2.w = f2tf32f(kt2.w);
            *(float4*)&Ks[row * FSTR + c * 8]     = ko;
            *(float4*)&Ks[row * FSTR + c * 8 + 4] = ko2;
            float4 vt = *(const float4*)(V + base + (size_t)row * DD + c * 8);
            float4 vt2 = *(const float4*)(V + base + (size_t)row * DD + c * 8 + 4);
            float4 vo, vo2;
            vo.x = f2tf32f(vt.x); vo.y = f2tf32f(vt.y); vo.z = f2tf32f(vt.z); vo.w = f2tf32f(vt.w);
            vo2.x = f2tf32f(vt2.x); vo2.y = f2tf32f(vt2.y); vo2.z = f2tf32f(vt2.z); vo2.w = f2tf32f(vt2.w);
            *(float4*)&Vs[row * FSTR + c * 8]     = vo;
            *(float4*)&Vs[row * FSTR + c * 8 + 4] = vo2;
        }
        __syncthreads();

        // ---- S = Qs @ Ks^T  (warp computes 16 x 64) ----
        float s[8][4];
        #pragma unroll
        for (int nt = 0; nt < 8; nt++)
            #pragma unroll
            for (int x = 0; x < 4; x++) s[nt][x] = 0.f;

        #pragma unroll
        for (int ks = 0; ks < 8; ks++) {
            const int kb = ks * 8;
            uint32_t a0 = __float_as_uint(Qs[(warp*16 + lr)     * FSTR + kb + lc]);
            uint32_t a1 = __float_as_uint(Qs[(warp*16 + lr + 8) * FSTR + kb + lc]);
            uint32_t a2 = __float_as_uint(Qs[(warp*16 + lr)     * FSTR + kb + 4 + lc]);
            uint32_t a3 = __float_as_uint(Qs[(warp*16 + lr + 8) * FSTR + kb + 4 + lc]);
            #pragma unroll
            for (int nt = 0; nt < 8; nt++) {
                uint32_t b0 = __float_as_uint(Ks[(nt*8 + lr) * FSTR + kb + lc]);
                uint32_t b1 = __float_as_uint(Ks[(nt*8 + lr) * FSTR + kb + 4 + lc]);
                asm volatile(
                    "mma.sync.aligned.m16n8k8.row.col.f32.tf32.tf32.f32 "
                    "{%0,%1,%2,%3}, {%4,%5,%6,%7}, {%8,%9}, {%0,%1,%2,%3};"
                    : "+f"(s[nt][0]), "+f"(s[nt][1]), "+f"(s[nt][2]), "+f"(s[nt][3])
                    : "r"(a0), "r"(a1), "r"(a2), "r"(a3), "r"(b0), "r"(b1));
            }
        }

        // ---- causal mask on diagonal tile ----
        if (t == qt) {
            #pragma unroll
            for (int nt = 0; nt < 8; nt++) {
                int c0 = nt * 8 + lc * 2;
                if (c0     > lw)     s[nt][0] = -1e30f;
                if (c0 + 1 > lw)     s[nt][1] = -1e30f;
                if (c0     > lw + 8) s[nt][2] = -1e30f;
                if (c0 + 1 > lw + 8) s[nt][3] = -1e30f;
            }
        }

        // ---- online softmax ----
        float tm0 = -1e30f, tm1 = -1e30f;
        #pragma unroll
        for (int nt = 0; nt < 8; nt++) {
            tm0 = fmaxf(tm0, fmaxf(s[nt][0], s[nt][1]));
            tm1 = fmaxf(tm1, fmaxf(s[nt][2], s[nt][3]));
        }
        tm0 = fmaxf(tm0, __shfl_xor_sync(0xffffffffu, tm0, 1));
        tm0 = fmaxf(tm0, __shfl_xor_sync(0xffffffffu, tm0, 2));
        tm1 = fmaxf(tm1, __shfl_xor_sync(0xffffffffu, tm1, 1));
        tm1 = fmaxf(tm1, __shfl_xor_sync(0xffffffffu, tm1, 2));

        const float mn0 = fmaxf(m0v, tm0);
        const float mn1 = fmaxf(m1v, tm1);
        const float cr0 = __expf(m0v - mn0);
        const float cr1 = __expf(m1v - mn1);
        l0 *= cr0; l1 *= cr1;
        #pragma unroll
        for (int nt = 0; nt < 8; nt++) {
            o_acc[nt][0] *= cr0; o_acc[nt][1] *= cr0;
            o_acc[nt][2] *= cr1; o_acc[nt][3] *= cr1;
        }
        m0v = mn0; m1v = mn1;

        // ---- P = exp(S - m), stage to Ps (warp-private rows) ----
        #pragma unroll
        for (int nt = 0; nt < 8; nt++) {
            float p0 = __expf(s[nt][0] - mn0);
            float p1 = __expf(s[nt][1] - mn0);
            float p2 = __expf(s[nt][2] - mn1);
            float p3 = __expf(s[nt][3] - mn1);
            l0 += p0 + p1;
            l1 += p2 + p3;
            *(float2*)&Ps[(warp*16 + lr)     * FSTR + nt*8 + lc*2] =
                make_float2(f2tf32f(p0), f2tf32f(p1));
            *(float2*)&Ps[(warp*16 + lr + 8) * FSTR + nt*8 + lc*2] =
                make_float2(f2tf32f(p2), f2tf32f(p3));
        }
        __syncwarp();

        // ---- O += P @ V ----
        #pragma unroll
        for (int ks = 0; ks < 8; ks++) {
            const int kb = ks * 8;
            uint32_t a0 = __float_as_uint(Ps[(warp*16 + lr)     * FSTR + kb + lc]);
            uint32_t a1 = __float_as_uint(Ps[(warp*16 + lr + 8) * FSTR + kb + lc]);
            uint32_t a2 = __float_as_uint(Ps[(warp*16 + lr)     * FSTR + kb + 4 + lc]);
            uint32_t a3 = __float_as_uint(Ps[(warp*16 + lr + 8) * FSTR + kb + 4 + lc]);
            #pragma unroll
            for (int nt = 0; nt < 8; nt++) {
                uint32_t b0 = __float_as_uint(Vs[(kb + lc)     * FSTR + nt*8 + lr]);
                uint32_t b1 = __float_as_uint(Vs[(kb + 4 + lc) * FSTR + nt*8 + lr]);
                asm volatile(
                    "mma.sync.aligned.m16n8k8.row.col.f32.tf32.tf32.f32 "
                    "{%0,%1,%2,%3}, {%4,%5,%6,%7}, {%8,%9}, {%0,%1,%2,%3};"
                    : "+f"(o_acc[nt][0]), "+f"(o_acc[nt][1]),
                      "+f"(o_acc[nt][2]), "+f"(o_acc[nt][3])
                    : "r"(a0), "r"(a1), "r"(a2), "r"(a3), "r"(b0), "r"(b1));
            }
        }
    }

    // ---- finalize ----
    l0 += __shfl_xor_sync(0xffffffffu, l0, 1);
    l0 += __shfl_xor_sync(0xffffffffu, l0, 2);
    l1 += __shfl_xor_sync(0xffffffffu, l1, 1);
    l1 += __shfl_xor_sync(0xffffffffu, l1, 2);
    const float inv0 = 1.0f / l0;
    const float inv1 = 1.0f / l1;

    const size_t obase = ((size_t)(b * SS + q0)) * DD + h * DKH;
    #pragma unroll
    for (int nt = 0; nt < 8; nt++) {
        int col = nt * 8 + lc * 2;
        *(float2*)(O + obase + (size_t)(warp*16 + lr) * DD + col) =
            make_float2(o_acc[nt][0] * inv0, o_acc[nt][1] * inv0);
        *(float2*)(O + obase + (size_t)(warp*16 + lr + 8) * DD + col) =
            make_float2(o_acc[nt][2] * inv1, o_acc[nt][3] * inv1);
    }
}

// ---------------- launch ----------------
extern "C" void kernel_launch(void* const* d_in, const int* in_sizes, int n_in,
                              void* d_out, int out_size)
{
    const float* q  = (const float*)d_in[0];
    const float* k  = (const float*)d_in[1];
    const float* v  = (const float*)d_in[2];
    // d_in[3] = mask (compile-time causal — unused)
    const float* wq = (const float*)d_in[4];
    const float* bq = (const float*)d_in[5];
    const float* wk = (const float*)d_in[6];
    const float* bk = (const float*)d_in[7];
    const float* wv = (const float*)d_in[8];
    const float* bv = (const float*)d_in[9];
    const float* wo = (const float*)d_in[10];
    const float* bo = (const float*)d_in[11];
    float* out = (float*)d_out;

    void *pQ, *pK, *pV, *pX;
    cudaGetSymbolAddress(&pQ, g_Q);
    cudaGetSymbolAddress(&pK, g_K);
    cudaGetSymbolAddress(&pV, g_V);
    cudaGetSymbolAddress(&pX, g_X);
    float* gQ = (float*)pQ;
    float* gK = (float*)pK;
    float* gV = (float*)pV;
    float* gX = (float*)pX;

    cudaFuncSetAttribute(flash_mma_kernel,
                         cudaFuncAttributeMaxDynamicSharedMemorySize, FLASH_SMEM);

    dim3 ggrid(DD / GBN, MROWS / GBM);   // (8, 32)
    gemm_tf32_kernel<<<ggrid, 256>>>(q, wq, bq, gQ, MROWS, DD, DD);
    gemm_tf32_kernel<<<ggrid, 256>>>(k, wk, bk, gK, MROWS, DD, DD);
    gemm_tf32_kernel<<<ggrid, 256>>>(v, wv, bv, gV, MROWS, DD, DD);

    dim3 fgrid(SS / FQT, NH, BB);        // (32, 16, 2)
    flash_mma_kernel<<<fgrid, 128, FLASH_SMEM>>>(gQ, gK, gV, gX);

    gemm_tf32_kernel<<<ggrid, 256>>>(gX, wo, bo, out, MROWS, DD, DD);
}

// round 5
// speedup vs baseline: 4.1436x; 1.6772x over previous
#include <cuda_runtime.h>
#include <cuda_bf16.h>
#include <math.h>
#include <stdint.h>

// Problem constants
#define BB 2
#define SS 2048
#define DD 1024
#define NH 16
#define DKH 64
#define MROWS (BB * SS)   // 4096

// ---------------- scratch (device globals; no allocation allowed) ----------------
__device__ float g_Q[MROWS * DD];
__device__ float g_K[MROWS * DD];
__device__ float g_V[MROWS * DD];
__device__ float g_X[MROWS * DD];
// tf32-preconverted copies
__device__ float g_qc[MROWS * DD];
__device__ float g_kc[MROWS * DD];
__device__ float g_vc[MROWS * DD];
__device__ float g_wc[4][DD * DD];

__device__ __forceinline__ uint32_t f2tf32(float x) {
    uint32_t r;
    asm("cvt.rna.tf32.f32 %0, %1;" : "=r"(r) : "f"(x));
    return r;
}
__device__ __forceinline__ float f2tf32f(float x) {
    return __uint_as_float(f2tf32(x));
}

__device__ __forceinline__ void cp_async16(uint32_t dst, const void* src) {
    asm volatile("cp.async.cg.shared.global [%0], [%1], 16;" :: "r"(dst), "l"(src));
}
#define CP_COMMIT()  asm volatile("cp.async.commit_group;")
#define CP_WAIT1()   asm volatile("cp.async.wait_group 1;")

// ---------------- elementwise tf32 conversion prep ----------------
__global__ __launch_bounds__(256) void cvt_tf32_prep(
    const float* __restrict__ in, float* __restrict__ out, int n4)
{
    int i = blockIdx.x * 256 + threadIdx.x;
    if (i < n4) {
        float4 t = ((const float4*)in)[i];
        t.x = f2tf32f(t.x); t.y = f2tf32f(t.y);
        t.z = f2tf32f(t.z); t.w = f2tf32f(t.w);
        ((float4*)out)[i] = t;
    }
}

// ---------------- TF32 GEMM, cp.async 3-stage pipeline ----------------
// C[4096,1024] = A[4096,1024] @ W[1024,1024]^T + bias. Inputs pre-rounded to tf32.
// BM=128, BN=128, BK=32; 256 thr = 8 warps (2m x 4n), warp tile 64x32, 4x4 m16n8k8.
// SMEM: [row][32] fp32, 16B chunks XOR-swizzled by (row&7) -> conflict-free frags.
#define GST 3
#define GSTAGE_FLOATS 8192          // A 128*32 + B 128*32
#define GEMM_SMEM (GST * GSTAGE_FLOATS * 4)   // 98304 B

__device__ __forceinline__ void gemm_stage_copy(
    const float* __restrict__ A, const float* __restrict__ W,
    int m0, int n0, int k0, uint32_t sA, uint32_t sB, int tid)
{
    #pragma unroll
    for (int u = 0; u < 4; u++) {
        int idx = tid + u * 256;
        int row = idx >> 3;           // 0..127
        int c   = idx & 7;            // 16B chunk in row
        int swz = c ^ (row & 7);
        cp_async16(sA + (uint32_t)(row * 128 + swz * 16),
                   A + (size_t)(m0 + row) * DD + k0 + c * 4);
        cp_async16(sB + (uint32_t)(row * 128 + swz * 16),
                   W + (size_t)(n0 + row) * DD + k0 + c * 4);
    }
}

__global__ __launch_bounds__(256) void gemm_tf32_ca(
    const float* __restrict__ A, const float* __restrict__ W,
    const float* __restrict__ bias, float* __restrict__ C, int round_out)
{
    extern __shared__ float sm[];
    const uint32_t sbase = (uint32_t)__cvta_generic_to_shared(sm);

    const int tid  = threadIdx.x;
    const int lane = tid & 31;
    const int warp = tid >> 5;
    const int wm = (warp & 1) * 64;
    const int wn = (warp >> 1) * 32;
    const int m0 = blockIdx.y * 128;
    const int n0 = blockIdx.x * 128;
    const int lr = lane >> 2;
    const int lc = lane & 3;

    float acc[4][4][4];
    #pragma unroll
    for (int i = 0; i < 4; i++)
        #pragma unroll
        for (int j = 0; j < 4; j++)
            #pragma unroll
            for (int t = 0; t < 4; t++) acc[i][j][t] = 0.f;

    const int NIT = DD / 32;   // 32

    // prologue: stages 0,1
    gemm_stage_copy(A, W, m0, n0, 0, sbase, sbase + 4096 * 4, tid);
    CP_COMMIT();
    gemm_stage_copy(A, W, m0, n0, 32,
                    sbase + GSTAGE_FLOATS * 4, sbase + (GSTAGE_FLOATS + 4096) * 4, tid);
    CP_COMMIT();

    for (int it = 0; it < NIT; it++) {
        CP_WAIT1();
        __syncthreads();

        // issue stage it+2 into slot (it+2)%3 (that slot's compute finished last iter)
        if (it + 2 < NIT) {
            int slot = (it + 2) % GST;
            gemm_stage_copy(A, W, m0, n0, (it + 2) * 32,
                            sbase + (uint32_t)(slot * GSTAGE_FLOATS) * 4,
                            sbase + (uint32_t)(slot * GSTAGE_FLOATS + 4096) * 4, tid);
        }
        CP_COMMIT();   // empty group when no copy -> keeps pending count stable

        const float* As = sm + (it % GST) * GSTAGE_FLOATS;
        const float* Bs = As + 4096;

        #pragma unroll
        for (int ks = 0; ks < 4; ks++) {
            const int sw0 = (((2 * ks)     ^ lr) << 2) + lc;
            const int sw1 = (((2 * ks + 1) ^ lr) << 2) + lc;
            uint32_t a[4][4], b[4][2];
            #pragma unroll
            for (int mt = 0; mt < 4; mt++) {
                int r = wm + mt * 16 + lr;
                a[mt][0] = __float_as_uint(As[r * 32 + sw0]);
                a[mt][1] = __float_as_uint(As[(r + 8) * 32 + sw0]);
                a[mt][2] = __float_as_uint(As[r * 32 + sw1]);
                a[mt][3] = __float_as_uint(As[(r + 8) * 32 + sw1]);
            }
            #pragma unroll
            for (int nt = 0; nt < 4; nt++) {
                int cn = wn + nt * 8 + lr;
                b[nt][0] = __float_as_uint(Bs[cn * 32 + sw0]);
                b[nt][1] = __float_as_uint(Bs[cn * 32 + sw1]);
            }
            #pragma unroll
            for (int mt = 0; mt < 4; mt++)
                #pragma unroll
                for (int nt = 0; nt < 4; nt++)
                    asm volatile(
                        "mma.sync.aligned.m16n8k8.row.col.f32.tf32.tf32.f32 "
                        "{%0,%1,%2,%3}, {%4,%5,%6,%7}, {%8,%9}, {%0,%1,%2,%3};"
                        : "+f"(acc[mt][nt][0]), "+f"(acc[mt][nt][1]),
                          "+f"(acc[mt][nt][2]), "+f"(acc[mt][nt][3])
                        : "r"(a[mt][0]), "r"(a[mt][1]), "r"(a[mt][2]), "r"(a[mt][3]),
                          "r"(b[nt][0]), "r"(b[nt][1]));
        }
    }

    #pragma unroll
    for (int nt = 0; nt < 4; nt++) {
        int col = n0 + wn + nt * 8 + lc * 2;
        float b0 = bias[col], b1 = bias[col + 1];
        #pragma unroll
        for (int mt = 0; mt < 4; mt++) {
            int r0 = m0 + wm + mt * 16 + lr;
            float2 o0, o1;
            if (round_out) {
                o0 = make_float2(f2tf32f(acc[mt][nt][0] + b0), f2tf32f(acc[mt][nt][1] + b1));
                o1 = make_float2(f2tf32f(acc[mt][nt][2] + b0), f2tf32f(acc[mt][nt][3] + b1));
            } else {
                o0 = make_float2(acc[mt][nt][0] + b0, acc[mt][nt][1] + b1);
                o1 = make_float2(acc[mt][nt][2] + b0, acc[mt][nt][3] + b1);
            }
            *(float2*)&C[(size_t)r0 * DD + col] = o0;
            *(float2*)&C[(size_t)(r0 + 8) * DD + col] = o1;
        }
    }
}

// ---------------- Flash attention (causal), TF32 mma, K/V reg-prefetch ----------------
// Inputs Q/K/V already tf32-rounded by GEMM epilogue; Q*0.125 is exact.
#define FQT 64
#define FKT 64
#define FSTR 68
#define FLASH_SMEM (4 * FQT * FSTR * 4)   // 69632 bytes

__global__ __launch_bounds__(128) void flash_mma_kernel(
    const float* __restrict__ Q, const float* __restrict__ K,
    const float* __restrict__ V, float* __restrict__ O)
{
    extern __shared__ float smem[];
    float* Qs = smem;
    float* Ks = smem + FQT * FSTR;
    float* Vs = smem + 2 * FQT * FSTR;
    float* Ps = smem + 3 * FQT * FSTR;

    const int tid  = threadIdx.x;
    const int lane = tid & 31;
    const int warp = tid >> 5;
    const int lr = lane >> 2;
    const int lc = lane & 3;
    const int qt = blockIdx.x;
    const int h  = blockIdx.y;
    const int b  = blockIdx.z;
    const int q0 = qt * FQT;
    const int lw = warp * 16 + lr;
    const float scale = 0.125f;

    // ---- load Q tile (x0.125, exact on tf32 values) ----
    {
        const size_t base = ((size_t)(b * SS + q0)) * DD + h * DKH;
        #pragma unroll
        for (int u = 0; u < 8; u++) {
            int idx = tid + u * 128;
            int row = idx >> 4;
            int c   = idx & 15;
            float4 t = *(const float4*)(Q + base + (size_t)row * DD + c * 4);
            t.x *= scale; t.y *= scale; t.z *= scale; t.w *= scale;
            *(float4*)&Qs[row * FSTR + c * 4] = t;
        }
    }

    float m0v = -1e30f, m1v = -1e30f, l0 = 0.f, l1 = 0.f;
    float o_acc[8][4];
    #pragma unroll
    for (int nt = 0; nt < 8; nt++)
        #pragma unroll
        for (int t = 0; t < 4; t++) o_acc[nt][t] = 0.f;

    const int ntiles = qt + 1;   // causal
    const int prow = (tid) >> 3;         // thread's copy row base (u stride 16 rows)
    const int pc   = tid & 7;

    // prefetch tile 0
    float4 pk0[4], pk1[4], pv0[4], pv1[4];
    {
        const size_t base = ((size_t)(b * SS)) * DD + h * DKH;
        #pragma unroll
        for (int u = 0; u < 4; u++) {
            int row = prow + u * 16;
            const float* kp = K + base + (size_t)row * DD + pc * 8;
            const float* vp = V + base + (size_t)row * DD + pc * 8;
            pk0[u] = *(const float4*)kp;       pk1[u] = *(const float4*)(kp + 4);
            pv0[u] = *(const float4*)vp;       pv1[u] = *(const float4*)(vp + 4);
        }
    }

    for (int t = 0; t < ntiles; t++) {
        __syncthreads();   // all warps done reading smem from prev tile (and Q store)
        // ---- store prefetched K/V tile ----
        #pragma unroll
        for (int u = 0; u < 4; u++) {
            int row = prow + u * 16;
            *(float4*)&Ks[row * FSTR + pc * 8]     = pk0[u];
            *(float4*)&Ks[row * FSTR + pc * 8 + 4] = pk1[u];
            *(float4*)&Vs[row * FSTR + pc * 8]     = pv0[u];
            *(float4*)&Vs[row * FSTR + pc * 8 + 4] = pv1[u];
        }
        // ---- prefetch tile t+1 ----
        if (t + 1 < ntiles) {
            const size_t base = ((size_t)(b * SS + (t + 1) * FKT)) * DD + h * DKH;
            #pragma unroll
            for (int u = 0; u < 4; u++) {
                int row = prow + u * 16;
                const float* kp = K + base + (size_t)row * DD + pc * 8;
                const float* vp = V + base + (size_t)row * DD + pc * 8;
                pk0[u] = *(const float4*)kp;   pk1[u] = *(const float4*)(kp + 4);
                pv0[u] = *(const float4*)vp;   pv1[u] = *(const float4*)(vp + 4);
            }
        }
        __syncthreads();

        // ---- S = Qs @ Ks^T ----
        float s[8][4];
        #pragma unroll
        for (int nt = 0; nt < 8; nt++)
            #pragma unroll
            for (int x = 0; x < 4; x++) s[nt][x] = 0.f;

        #pragma unroll
        for (int ks = 0; ks < 8; ks++) {
            const int kb = ks * 8;
            uint32_t a0 = __float_as_uint(Qs[(warp*16 + lr)     * FSTR + kb + lc]);
            uint32_t a1 = __float_as_uint(Qs[(warp*16 + lr + 8) * FSTR + kb + lc]);
            uint32_t a2 = __float_as_uint(Qs[(warp*16 + lr)     * FSTR + kb + 4 + lc]);
            uint32_t a3 = __float_as_uint(Qs[(warp*16 + lr + 8) * FSTR + kb + 4 + lc]);
            #pragma unroll
            for (int nt = 0; nt < 8; nt++) {
                uint32_t b0 = __float_as_uint(Ks[(nt*8 + lr) * FSTR + kb + lc]);
                uint32_t b1 = __float_as_uint(Ks[(nt*8 + lr) * FSTR + kb + 4 + lc]);
                asm volatile(
                    "mma.sync.aligned.m16n8k8.row.col.f32.tf32.tf32.f32 "
                    "{%0,%1,%2,%3}, {%4,%5,%6,%7}, {%8,%9}, {%0,%1,%2,%3};"
                    : "+f"(s[nt][0]), "+f"(s[nt][1]), "+f"(s[nt][2]), "+f"(s[nt][3])
                    : "r"(a0), "r"(a1), "r"(a2), "r"(a3), "r"(b0), "r"(b1));
            }
        }

        // ---- causal mask on diagonal tile ----
        if (t == qt) {
            #pragma unroll
            for (int nt = 0; nt < 8; nt++) {
                int c0 = nt * 8 + lc * 2;
                if (c0     > lw)     s[nt][0] = -1e30f;
                if (c0 + 1 > lw)     s[nt][1] = -1e30f;
                if (c0     > lw + 8) s[nt][2] = -1e30f;
                if (c0 + 1 > lw + 8) s[nt][3] = -1e30f;
            }
        }

        // ---- online softmax ----
        float tm0 = -1e30f, tm1 = -1e30f;
        #pragma unroll
        for (int nt = 0; nt < 8; nt++) {
            tm0 = fmaxf(tm0, fmaxf(s[nt][0], s[nt][1]));
            tm1 = fmaxf(tm1, fmaxf(s[nt][2], s[nt][3]));
        }
        tm0 = fmaxf(tm0, __shfl_xor_sync(0xffffffffu, tm0, 1));
        tm0 = fmaxf(tm0, __shfl_xor_sync(0xffffffffu, tm0, 2));
        tm1 = fmaxf(tm1, __shfl_xor_sync(0xffffffffu, tm1, 1));
        tm1 = fmaxf(tm1, __shfl_xor_sync(0xffffffffu, tm1, 2));

        const float mn0 = fmaxf(m0v, tm0);
        const float mn1 = fmaxf(m1v, tm1);
        const float cr0 = __expf(m0v - mn0);
        const float cr1 = __expf(m1v - mn1);
        l0 *= cr0; l1 *= cr1;
        #pragma unroll
        for (int nt = 0; nt < 8; nt++) {
            o_acc[nt][0] *= cr0; o_acc[nt][1] *= cr0;
            o_acc[nt][2] *= cr1; o_acc[nt][3] *= cr1;
        }
        m0v = mn0; m1v = mn1;

        // ---- P = exp(S - m) -> Ps (warp-private rows) ----
        #pragma unroll
        for (int nt = 0; nt < 8; nt++) {
            float p0 = __expf(s[nt][0] - mn0);
            float p1 = __expf(s[nt][1] - mn0);
            float p2 = __expf(s[nt][2] - mn1);
            float p3 = __expf(s[nt][3] - mn1);
            l0 += p0 + p1;
            l1 += p2 + p3;
            *(float2*)&Ps[(warp*16 + lr)     * FSTR + nt*8 + lc*2] =
                make_float2(f2tf32f(p0), f2tf32f(p1));
            *(float2*)&Ps[(warp*16 + lr + 8) * FSTR + nt*8 + lc*2] =
                make_float2(f2tf32f(p2), f2tf32f(p3));
        }
        __syncwarp();

        // ---- O += P @ V ----
        #pragma unroll
        for (int ks = 0; ks < 8; ks++) {
            const int kb = ks * 8;
            uint32_t a0 = __float_as_uint(Ps[(warp*16 + lr)     * FSTR + kb + lc]);
            uint32_t a1 = __float_as_uint(Ps[(warp*16 + lr + 8) * FSTR + kb + lc]);
            uint32_t a2 = __float_as_uint(Ps[(warp*16 + lr)     * FSTR + kb + 4 + lc]);
            uint32_t a3 = __float_as_uint(Ps[(warp*16 + lr + 8) * FSTR + kb + 4 + lc]);
            #pragma unroll
            for (int nt = 0; nt < 8; nt++) {
                uint32_t b0 = __float_as_uint(Vs[(kb + lc)     * FSTR + nt*8 + lr]);
                uint32_t b1 = __float_as_uint(Vs[(kb + 4 + lc) * FSTR + nt*8 + lr]);
                asm volatile(
                    "mma.sync.aligned.m16n8k8.row.col.f32.tf32.tf32.f32 "
                    "{%0,%1,%2,%3}, {%4,%5,%6,%7}, {%8,%9}, {%0,%1,%2,%3};"
                    : "+f"(o_acc[nt][0]), "+f"(o_acc[nt][1]),
                      "+f"(o_acc[nt][2]), "+f"(o_acc[nt][3])
                    : "r"(a0), "r"(a1), "r"(a2), "r"(a3), "r"(b0), "r"(b1));
            }
        }
    }

    // ---- finalize (tf32-rounded X for the cp.async output GEMM) ----
    l0 += __shfl_xor_sync(0xffffffffu, l0, 1);
    l0 += __shfl_xor_sync(0xffffffffu, l0, 2);
    l1 += __shfl_xor_sync(0xffffffffu, l1, 1);
    l1 += __shfl_xor_sync(0xffffffffu, l1, 2);
    const float inv0 = 1.0f / l0;
    const float inv1 = 1.0f / l1;

    const size_t obase = ((size_t)(b * SS + q0)) * DD + h * DKH;
    #pragma unroll
    for (int nt = 0; nt < 8; nt++) {
        int col = nt * 8 + lc * 2;
        *(float2*)(O + obase + (size_t)(warp*16 + lr) * DD + col) =
            make_float2(f2tf32f(o_acc[nt][0] * inv0), f2tf32f(o_acc[nt][1] * inv0));
        *(float2*)(O + obase + (size_t)(warp*16 + lr + 8) * DD + col) =
            make_float2(f2tf32f(o_acc[nt][2] * inv1), f2tf32f(o_acc[nt][3] * inv1));
    }
}

// ---------------- launch ----------------
extern "C" void kernel_launch(void* const* d_in, const int* in_sizes, int n_in,
                              void* d_out, int out_size)
{
    const float* q  = (const float*)d_in[0];
    const float* k  = (const float*)d_in[1];
    const float* v  = (const float*)d_in[2];
    // d_in[3] = mask (compile-time causal — unused)
    const float* wq = (const float*)d_in[4];
    const float* bq = (const float*)d_in[5];
    const float* wk = (const float*)d_in[6];
    const float* bk = (const float*)d_in[7];
    const float* wv = (const float*)d_in[8];
    const float* bv = (const float*)d_in[9];
    const float* wo = (const float*)d_in[10];
    const float* bo = (const float*)d_in[11];
    float* out = (float*)d_out;

    void *pQ, *pK, *pV, *pX, *pqc, *pkc, *pvc, *pwc;
    cudaGetSymbolAddress(&pQ, g_Q);
    cudaGetSymbolAddress(&pK, g_K);
    cudaGetSymbolAddress(&pV, g_V);
    cudaGetSymbolAddress(&pX, g_X);
    cudaGetSymbolAddress(&pqc, g_qc);
    cudaGetSymbolAddress(&pkc, g_kc);
    cudaGetSymbolAddress(&pvc, g_vc);
    cudaGetSymbolAddress(&pwc, g_wc);
    float* gQ = (float*)pQ;   float* gK = (float*)pK;
    float* gV = (float*)pV;   float* gX = (float*)pX;
    float* qc = (float*)pqc;  float* kc = (float*)pkc;
    float* vc = (float*)pvc;
    float* wqc = (float*)pwc;
    float* wkc = wqc + DD * DD;
    float* wvc = wqc + 2 * DD * DD;
    float* woc = wqc + 3 * DD * DD;

    cudaFuncSetAttribute(flash_mma_kernel,
                         cudaFuncAttributeMaxDynamicSharedMemorySize, FLASH_SMEM);
    cudaFuncSetAttribute(gemm_tf32_ca,
                         cudaFuncAttributeMaxDynamicSharedMemorySize, GEMM_SMEM);

    // prep: tf32 conversions
    const int nin4 = MROWS * DD / 4;   // 1M
    const int nw4  = DD * DD / 4;      // 256K
    cvt_tf32_prep<<<nin4 / 256, 256>>>(q, qc, nin4);
    cvt_tf32_prep<<<nin4 / 256, 256>>>(k, kc, nin4);
    cvt_tf32_prep<<<nin4 / 256, 256>>>(v, vc, nin4);
    cvt_tf32_prep<<<nw4 / 256, 256>>>(wq, wqc, nw4);
    cvt_tf32_prep<<<nw4 / 256, 256>>>(wk, wkc, nw4);
    cvt_tf32_prep<<<nw4 / 256, 256>>>(wv, wvc, nw4);
    cvt_tf32_prep<<<nw4 / 256, 256>>>(wo, woc, nw4);

    dim3 ggrid(DD / 128, MROWS / 128);   // (8, 32)
    gemm_tf32_ca<<<ggrid, 256, GEMM_SMEM>>>(qc, wqc, bq, gQ, 1);
    gemm_tf32_ca<<<ggrid, 256, GEMM_SMEM>>>(kc, wkc, bk, gK, 1);
    gemm_tf32_ca<<<ggrid, 256, GEMM_SMEM>>>(vc, wvc, bv, gV, 1);

    dim3 fgrid(SS / FQT, NH, BB);        // (32, 16, 2)
    flash_mma_kernel<<<fgrid, 128, FLASH_SMEM>>>(gQ, gK, gV, gX);

    gemm_tf32_ca<<<ggrid, 256, GEMM_SMEM>>>(gX, woc, bo, out, 0);
}